// round 7
// baseline (speedup 1.0000x reference)
#include <cuda_runtime.h>
#include <cuda_bf16.h>
#include <cstdint>

// Problem constants
#define B_ 4
#define T_ 4096
#define C_ 2048
#define H_ 16
#define D_ 128
#define L_ 64
#define HL_ 1024
#define SCALE_ 0.08838834764831845f  // 1/sqrt(128)

// Scratch (device globals; no allocations allowed)
__device__ float g_klin[4][256 * C_];                   // split-K partials
__device__ float g_vlin[4][256 * C_];
__device__ float g_kbuf[B_ * H_ * 64 * D_];
__device__ float g_vbuf[B_ * H_ * 64 * D_];
__device__ float g_attn[B_ * H_ * L_ * D_];
__device__ float g_P[(long)B_ * HL_ * C_];              // P = attn @ Wp (fp32)
__device__ __nv_bfloat16 g_xb[(long)B_ * T_ * C_];      // x in bf16
__device__ __nv_bfloat16 g_WgTb[(long)HL_ * C_];        // Wg^T bf16 [N=1024,K=2048]
__device__ __nv_bfloat16 g_Gb[(long)B_ * T_ * HL_];     // softmaxed gates bf16
__device__ __nv_bfloat16 g_PTb[(long)B_ * C_ * HL_];    // P^T bf16 [b][N=2048,K=1024]

__device__ __forceinline__ uint32_t smem_u32(const void* p) {
    uint32_t a;
    asm("{ .reg .u64 t; cvta.to.shared.u64 t, %1; cvt.u32.u64 %0, t; }" : "=r"(a) : "l"(p));
    return a;
}

#define CP_ASYNC16(dst, src) \
    asm volatile("cp.async.cg.shared.global [%0], [%1], 16;" :: "r"(dst), "l"(src) : "memory")
#define CP_COMMIT() asm volatile("cp.async.commit_group;" ::: "memory")
#define CP_WAIT1()  asm volatile("cp.async.wait_group 1;" ::: "memory")

#define LDMATRIX_X4(r0, r1, r2, r3, addr) \
    asm volatile("ldmatrix.sync.aligned.m8n8.x4.shared.b16 {%0,%1,%2,%3}, [%4];" \
        : "=r"(r0), "=r"(r1), "=r"(r2), "=r"(r3) : "r"(addr))

__device__ __forceinline__ void mma_bf16(
    float& d0, float& d1, float& d2, float& d3,
    uint32_t a0, uint32_t a1, uint32_t a2, uint32_t a3,
    uint32_t b0, uint32_t b1)
{
    asm volatile(
        "mma.sync.aligned.m16n8k16.row.col.f32.bf16.bf16.f32 "
        "{%0,%1,%2,%3}, {%4,%5,%6,%7}, {%8,%9}, {%0,%1,%2,%3};"
        : "+f"(d0), "+f"(d1), "+f"(d2), "+f"(d3)
        : "r"(a0), "r"(a1), "r"(a2), "r"(a3), "r"(b0), "r"(b1));
}

// ============================================================================
// bf16 mma.sync GEMM: C[M,N] = A[M,K] @ B[N,K]^T, bf16 in.
// CTA 128x128, K-tile 64 (128B rows, XOR-swizzled), 3-stage cp.async pipeline.
// GATE=false: fp32 output. GATE=true: fused per-row softmax over contiguous
// 64-col groups (x SCALE_), bf16 output.
// ============================================================================
#define STG 3
#define TILE_BYTES 16384                 // 128 rows * 128B
#define STAGE_BYTES (2 * TILE_BYTES)     // A + B
#define GEMM_SMEM (STG * STAGE_BYTES)    // 98304
#define PS_ 130                          // epilogue smem row stride (floats)

template<bool GATE>
__global__ __launch_bounds__(256, 2) void gemm_bf16_t(
    const __nv_bfloat16* __restrict__ A, const __nv_bfloat16* __restrict__ B,
    void* __restrict__ Cout,
    int K, int lda, int ldb, int ldc, long sA, long sB, long sC)
{
    extern __shared__ char sm[];
    const uint32_t sbase = smem_u32(sm);
    A += (long)blockIdx.z * sA;
    B += (long)blockIdx.z * sB;
    const int bm = blockIdx.y * 128;
    const int bn = blockIdx.x * 128;
    const int tid  = threadIdx.x;
    const int wid  = tid >> 5;
    const int lane = tid & 31;
    const int wm = (wid & 1) * 64;
    const int wn = (wid >> 1) * 32;

    const __nv_bfloat16* Ag = A + (long)bm * lda;
    const __nv_bfloat16* Bg = B + (long)bn * ldb;

    float acc[4][4][4];
    #pragma unroll
    for (int i = 0; i < 4; i++)
        #pragma unroll
        for (int j = 0; j < 4; j++)
            #pragma unroll
            for (int f = 0; f < 4; f++) acc[i][j][f] = 0.f;

    const int nt = K >> 6;

    auto load_stage = [&](int t) {
        const int s = t % STG;
        const uint32_t ab = sbase + s * STAGE_BYTES;
        const uint32_t bb = ab + TILE_BYTES;
        const char* as0 = (const char*)(Ag + (long)t * 64);
        const char* bs0 = (const char*)(Bg + (long)t * 64);
        #pragma unroll
        for (int q = 0; q < 4; q++) {
            int chunk = tid + q * 256;
            int row = chunk >> 3;
            int c   = chunk & 7;
            uint32_t off = row * 128 + ((c ^ (row & 7)) << 4);
            CP_ASYNC16(ab + off, as0 + (long)row * lda * 2 + c * 16);
            CP_ASYNC16(bb + off, bs0 + (long)row * ldb * 2 + c * 16);
        }
    };

    load_stage(0); CP_COMMIT();
    load_stage(1); CP_COMMIT();

    const int a_row_l  = lane & 15;
    const int a_chu_l  = lane >> 4;
    const int b_g      = lane >> 3;
    const int b_row_l  = (lane & 7) + ((b_g >> 1) << 3);
    const int b_chu_l  = b_g & 1;

    for (int t = 0; t < nt; t++) {
        CP_WAIT1();
        __syncthreads();
        if (t + 2 < nt) load_stage(t + 2);
        CP_COMMIT();

        const int s = t % STG;
        const uint32_t ab = sbase + s * STAGE_BYTES;
        const uint32_t bb = ab + TILE_BYTES;

        #pragma unroll
        for (int ks = 0; ks < 4; ks++) {
            uint32_t a[4][4], b[2][4];
            #pragma unroll
            for (int i = 0; i < 4; i++) {
                int r = wm + i * 16 + a_row_l;
                int c = ks * 2 + a_chu_l;
                uint32_t addr = ab + r * 128 + ((c ^ (r & 7)) << 4);
                LDMATRIX_X4(a[i][0], a[i][1], a[i][2], a[i][3], addr);
            }
            #pragma unroll
            for (int j2 = 0; j2 < 2; j2++) {
                int n = wn + j2 * 16 + b_row_l;
                int c = ks * 2 + b_chu_l;
                uint32_t addr = bb + n * 128 + ((c ^ (n & 7)) << 4);
                LDMATRIX_X4(b[j2][0], b[j2][1], b[j2][2], b[j2][3], addr);
            }
            #pragma unroll
            for (int i = 0; i < 4; i++)
                #pragma unroll
                for (int j = 0; j < 4; j++)
                    mma_bf16(acc[i][j][0], acc[i][j][1], acc[i][j][2], acc[i][j][3],
                             a[i][0], a[i][1], a[i][2], a[i][3],
                             b[j >> 1][(j & 1) * 2], b[j >> 1][(j & 1) * 2 + 1]);
        }
    }

    const int lr = lane >> 2;
    const int lc = lane & 3;

    if (!GATE) {
        float* C = (float*)Cout + (long)blockIdx.z * sC;
        #pragma unroll
        for (int i = 0; i < 4; i++) {
            int r0 = bm + wm + i * 16 + lr;
            #pragma unroll
            for (int j = 0; j < 4; j++) {
                int col = bn + wn + j * 8 + 2 * lc;
                *(float2*)(C + (long)r0 * ldc + col)       = make_float2(acc[i][j][0], acc[i][j][1]);
                *(float2*)(C + (long)(r0 + 8) * ldc + col) = make_float2(acc[i][j][2], acc[i][j][3]);
            }
        }
    } else {
        // fused gate softmax: spill tile to smem, softmax each 64-col group
        __syncthreads();   // all warps done with stage smem
        float* st = (float*)sm;
        #pragma unroll
        for (int i = 0; i < 4; i++) {
            int r = wm + i * 16 + lr;
            #pragma unroll
            for (int j = 0; j < 4; j++) {
                int c = wn + j * 8 + 2 * lc;
                *(float2*)(st + r * PS_ + c)       = make_float2(acc[i][j][0], acc[i][j][1]);
                *(float2*)(st + (r + 8) * PS_ + c) = make_float2(acc[i][j][2], acc[i][j][3]);
            }
        }
        __syncthreads();
        const int r = tid >> 1, g = tid & 1;
        float2* rowp = (float2*)(st + r * PS_ + g * 64);
        float m = -1e30f;
        #pragma unroll
        for (int i = 0; i < 32; i++) {
            float2 v = rowp[i];
            m = fmaxf(m, fmaxf(v.x, v.y));
        }
        float sum = 0.f;
        #pragma unroll
        for (int i = 0; i < 32; i++) {
            float2 v = rowp[i];
            v.x = __expf((v.x - m) * SCALE_);
            v.y = __expf((v.y - m) * SCALE_);
            sum += v.x + v.y;
            rowp[i] = v;
        }
        float inv = 1.f / sum;
        __nv_bfloat16* go = (__nv_bfloat16*)Cout + (long)(bm + r) * ldc + bn + g * 64;
        #pragma unroll
        for (int q = 0; q < 8; q++) {
            float2 v0 = rowp[q * 4 + 0];
            float2 v1 = rowp[q * 4 + 1];
            float2 v2 = rowp[q * 4 + 2];
            float2 v3 = rowp[q * 4 + 3];
            uint4 o;
            __nv_bfloat162 p0 = __float22bfloat162_rn(make_float2(v0.x * inv, v0.y * inv));
            __nv_bfloat162 p1 = __float22bfloat162_rn(make_float2(v1.x * inv, v1.y * inv));
            __nv_bfloat162 p2 = __float22bfloat162_rn(make_float2(v2.x * inv, v2.y * inv));
            __nv_bfloat162 p3 = __float22bfloat162_rn(make_float2(v3.x * inv, v3.y * inv));
            o.x = *(uint32_t*)&p0; o.y = *(uint32_t*)&p1;
            o.z = *(uint32_t*)&p2; o.w = *(uint32_t*)&p3;
            ((uint4*)go)[q] = o;
        }
    }
}

// ============================================================================
// x -> bf16 conversion
// ============================================================================
__global__ void convert_x(const float* __restrict__ x)
{
    long i = (long)blockIdx.x * blockDim.x + threadIdx.x;
    const long n4 = (long)B_ * T_ * C_ / 4;
    if (i >= n4) return;
    float4 v = ((const float4*)x)[i];
    __nv_bfloat16* o = g_xb + i * 4;
    o[0] = __float2bfloat16(v.x);
    o[1] = __float2bfloat16(v.y);
    o[2] = __float2bfloat16(v.z);
    o[3] = __float2bfloat16(v.w);
}

// ============================================================================
// 64x128x8 SIMT fp32 GEMM tile (small GEMMs: kv projection, P)
// ============================================================================
__device__ __forceinline__ void gemm64_body(
    const float* __restrict__ A, int lda,
    const float* __restrict__ B, int ldb,
    float* __restrict__ C, int ldc, int K, int bn)
{
    __shared__ __align__(16) float As[8][64];
    __shared__ __align__(16) float Bs[8][128];
    const int tid = threadIdx.x;
    const int arow = tid >> 2;
    const int acol = (tid & 3) * 2;
    const int brow = tid >> 5;
    const int bcol = (tid & 31) * 4;
    const int tx = (tid & 15) * 8;
    const int ty = (tid >> 4) * 4;

    float acc[4][8];
    #pragma unroll
    for (int i = 0; i < 4; i++)
        #pragma unroll
        for (int j = 0; j < 8; j++) acc[i][j] = 0.f;

    const float* Ap = A + (long)arow * lda + acol;
    const float* Bp = B + (long)brow * ldb + bn + bcol;
    for (int k0 = 0; k0 < K; k0 += 8) {
        float2 a2 = *(const float2*)Ap;
        float4 b4 = *(const float4*)Bp;
        As[acol + 0][arow] = a2.x;
        As[acol + 1][arow] = a2.y;
        *(float4*)&Bs[brow][bcol] = b4;
        __syncthreads();
        #pragma unroll
        for (int kk = 0; kk < 8; kk++) {
            float4 a0 = *(const float4*)&As[kk][ty];
            float4 b0 = *(const float4*)&Bs[kk][tx];
            float4 b1 = *(const float4*)&Bs[kk][tx + 4];
            float ar[4] = {a0.x, a0.y, a0.z, a0.w};
            float br[8] = {b0.x, b0.y, b0.z, b0.w, b1.x, b1.y, b1.z, b1.w};
            #pragma unroll
            for (int i = 0; i < 4; i++)
                #pragma unroll
                for (int j = 0; j < 8; j++)
                    acc[i][j] = fmaf(ar[i], br[j], acc[i][j]);
        }
        __syncthreads();
        Ap += 8;
        Bp += (long)8 * ldb;
    }
    #pragma unroll
    for (int i = 0; i < 4; i++) {
        float* crow = C + (long)(ty + i) * ldc + bn + tx;
        *(float4*)(crow)     = make_float4(acc[i][0], acc[i][1], acc[i][2], acc[i][3]);
        *(float4*)(crow + 4) = make_float4(acc[i][4], acc[i][5], acc[i][6], acc[i][7]);
    }
}

// kv projection, split-K x4: y = K-slice, z = b*2 + which
__global__ __launch_bounds__(256) void kv_gemm(
    const float* __restrict__ x, const float* __restrict__ Wk, const float* __restrict__ Wv)
{
    int z = blockIdx.z;
    int s = blockIdx.y;                 // K slice 0..3 (chunks of 512)
    int b = z >> 1, which = z & 1;
    const float* A = x + (long)b * T_ * C_ + s * 512;
    const float* Bm = (which ? Wv : Wk) + (long)s * 512 * C_;
    float* Cm = (which ? g_vlin[s] : g_klin[s]) + (long)b * 64 * C_;
    gemm64_body(A, C_, Bm, C_, Cm, C_, 512, blockIdx.x * 128);
}

__global__ __launch_bounds__(256) void p_gemm(const float* __restrict__ Wp)
{
    int z = blockIdx.z;
    int b = z >> 4, h = z & 15;
    const float* A = g_attn + (long)z * L_ * D_;
    const float* Bm = Wp + (long)h * D_ * C_;
    float* Cm = g_P + (long)b * HL_ * C_ + (long)h * L_ * C_;
    gemm64_body(A, D_, Bm, C_, Cm, C_, D_, blockIdx.x * 128);
}

// ============================================================================
// transposes (-> bf16)
// ============================================================================
__global__ void transpose_wg(const float* __restrict__ Wg)
{
    __shared__ float tile[32][33];
    int k0 = blockIdx.x * 32, n0 = blockIdx.y * 32;
    int tx = threadIdx.x & 31, ty = threadIdx.x >> 5;
    #pragma unroll
    for (int i = 0; i < 32; i += 8)
        tile[ty + i][tx] = Wg[(long)(k0 + ty + i) * HL_ + n0 + tx];
    __syncthreads();
    #pragma unroll
    for (int i = 0; i < 32; i += 8)
        g_WgTb[(long)(n0 + ty + i) * C_ + k0 + tx] = __float2bfloat16(tile[tx][ty + i]);
}

__global__ void transpose_p()
{
    __shared__ float tile[32][33];
    int b = blockIdx.z;
    int hl0 = blockIdx.x * 32, c0 = blockIdx.y * 32;
    const float* P = g_P + (long)b * HL_ * C_;
    __nv_bfloat16* PT = g_PTb + (long)b * C_ * HL_;
    int tx = threadIdx.x & 31, ty = threadIdx.x >> 5;
    #pragma unroll
    for (int i = 0; i < 32; i += 8)
        tile[ty + i][tx] = P[(long)(hl0 + ty + i) * C_ + c0 + tx];
    __syncthreads();
    #pragma unroll
    for (int i = 0; i < 32; i += 8)
        PT[(long)(c0 + ty + i) * HL_ + hl0 + tx] = __float2bfloat16(tile[tx][ty + i]);
}

// ============================================================================
// rope + reduce split-K partials + transpose k,v for first 64 tokens
// ============================================================================
__global__ void rope_kernel()
{
    int idx = blockIdx.x * blockDim.x + threadIdx.x;
    if (idx >= B_ * 64 * H_ * 64) return;
    int j = idx & 63;
    int h = (idx >> 6) & 15;
    int t = (idx >> 10) & 63;
    int b = idx >> 16;
    long src = (long)(b * 64 + t) * C_ + h * D_ + 2 * j;
    float x0 = 0.f, x1 = 0.f, v0 = 0.f, v1 = 0.f;
    #pragma unroll
    for (int s = 0; s < 4; s++) {
        x0 += g_klin[s][src];
        x1 += g_klin[s][src + 1];
        v0 += g_vlin[s][src];
        v1 += g_vlin[s][src + 1];
    }
    float inv_freq = expf(-(float)j * 0.14391156831f);  // ln(10000)/64
    float ang = (float)t * inv_freq;
    float c = cosf(ang), s = sinf(ang);
    long dst = ((long)((b * H_ + h) * 64 + t)) * D_ + 2 * j;
    g_kbuf[dst] = x0 * c - x1 * s;
    g_kbuf[dst + 1] = x0 * s + x1 * c;
    g_vbuf[dst] = v0;
    g_vbuf[dst + 1] = v1;
}

// ============================================================================
// latent attention: per (b,h) 64x64 causal softmax @ v
// ============================================================================
__global__ void attn_kernel(const float* __restrict__ lq)
{
    int b = blockIdx.x >> 4, h = blockIdx.x & 15;
    __shared__ float ks[64][D_];
    __shared__ float sc[64];
    __shared__ float red[2][64];
    const float* kb = g_kbuf + (long)((b * H_ + h) * 64) * D_;
    const float* vb = g_vbuf + (long)((b * H_ + h) * 64) * D_;
    float* ao = g_attn + (long)((b * H_ + h) * L_) * D_;
    int tid = threadIdx.x;
    for (int i = tid; i < 64 * D_; i += 128) ks[i >> 7][i & 127] = kb[i];
    __syncthreads();

    for (int l = 0; l < L_; l++) {
        const float* q = lq + (long)(l * H_ + h) * D_;
        int t = tid & 63, part = tid >> 6;
        float dot = 0.f;
        if (t <= l) {
            int d0 = part * 64;
            #pragma unroll 8
            for (int d = d0; d < d0 + 64; d++) dot = fmaf(q[d], ks[t][d], dot);
        }
        red[part][t] = dot;
        __syncthreads();
        if (tid < 64) sc[tid] = (red[0][tid] + red[1][tid]) * SCALE_;
        __syncthreads();
        if (tid < 32) {
            float m = -1e30f;
            for (int t2 = tid; t2 <= l; t2 += 32) m = fmaxf(m, sc[t2]);
            #pragma unroll
            for (int o = 16; o; o >>= 1) m = fmaxf(m, __shfl_xor_sync(0xffffffffu, m, o));
            float s = 0.f;
            for (int t2 = tid; t2 <= l; t2 += 32) {
                float e = expf(sc[t2] - m);
                sc[t2] = e;
                s += e;
            }
            #pragma unroll
            for (int o = 16; o; o >>= 1) s += __shfl_xor_sync(0xffffffffu, s, o);
            if (tid == 0) red[0][0] = s;
        }
        __syncthreads();
        float inv = 1.f / red[0][0];
        float acc = 0.f;
        for (int t2 = 0; t2 <= l; t2++) acc = fmaf(sc[t2], vb[(long)t2 * D_ + tid], acc);
        ao[(long)l * D_ + tid] = acc * inv;
        __syncthreads();
    }
}

// ============================================================================
extern "C" void kernel_launch(void* const* d_in, const int* in_sizes, int n_in,
                              void* d_out, int out_size)
{
    const float* x  = (const float*)d_in[0];
    const float* lq = (const float*)d_in[1];
    const float* Wk = (const float*)d_in[2];
    const float* Wv = (const float*)d_in[3];
    const float* Wg = (const float*)d_in[4];
    const float* Wp = (const float*)d_in[5];
    float* out = (float*)d_out;

    __nv_bfloat16 *xb, *WgTb, *Gb, *PTb;
    cudaGetSymbolAddress((void**)&xb, g_xb);
    cudaGetSymbolAddress((void**)&WgTb, g_WgTb);
    cudaGetSymbolAddress((void**)&Gb, g_Gb);
    cudaGetSymbolAddress((void**)&PTb, g_PTb);

    cudaFuncSetAttribute(gemm_bf16_t<false>, cudaFuncAttributeMaxDynamicSharedMemorySize, GEMM_SMEM);
    cudaFuncSetAttribute(gemm_bf16_t<true>,  cudaFuncAttributeMaxDynamicSharedMemorySize, GEMM_SMEM);

    // 1. x -> bf16
    convert_x<<<(int)(((long)B_ * T_ * C_ / 4 + 255) / 256), 256>>>(x);
    // 2. k,v for first 64 tokens per batch, split-K x4
    kv_gemm<<<dim3(16, 4, 8), 256>>>(x, Wk, Wv);
    // 3. rope + partial-sum reduce + transpose
    rope_kernel<<<(B_ * 64 * H_ * 64 + 255) / 256, 256>>>();
    // 4. WgT -> bf16
    transpose_wg<<<dim3(C_ / 32, HL_ / 32), 256>>>(Wg);
    // 5. Gb = softmax(x @ WgT^T * SCALE) fused (bf16 mma + epilogue softmax)
    gemm_bf16_t<true><<<dim3(HL_ / 128, (B_ * T_) / 128, 1), 256, GEMM_SMEM>>>(
        xb, WgTb, Gb, C_, C_, C_, HL_, 0, 0, 0);
    // 6. latent attention
    attn_kernel<<<B_ * H_, 128>>>(lq);
    // 7. P = attn @ Wp blocks (fp32)
    p_gemm<<<dim3(C_ / 128, 1, B_ * H_), 256>>>(Wp);
    // 8. PT -> bf16 per batch
    transpose_p<<<dim3(HL_ / 32, C_ / 32, B_), 256>>>();
    // 9. out = G @ PT^T per batch (bf16 mma), [4096,2048], K=1024
    gemm_bf16_t<false><<<dim3(C_ / 128, T_ / 128, B_), 256, GEMM_SMEM>>>(
        Gb, PTb, out, HL_, HL_, HL_, C_,
        (long)T_ * HL_, (long)C_ * HL_, (long)T_ * C_);
}

// round 9
// speedup vs baseline: 1.7771x; 1.7771x over previous
#include <cuda_runtime.h>
#include <cuda_bf16.h>
#include <cstdint>

// Problem constants
#define B_ 4
#define T_ 4096
#define C_ 2048
#define H_ 16
#define D_ 128
#define L_ 64
#define HL_ 1024
#define SCALE_ 0.08838834764831845f  // 1/sqrt(128)

// Scratch (device globals; no allocations allowed)
__device__ float g_klin[4][256 * C_];                   // split-K partials
__device__ float g_vlin[4][256 * C_];
__device__ float g_kbuf[B_ * H_ * 64 * D_];
__device__ float g_vbuf[B_ * H_ * 64 * D_];
__device__ float g_attn[B_ * H_ * L_ * D_];
__device__ float g_G[(long)B_ * T_ * HL_];              // gate logits (fp32)
__device__ float g_P[(long)B_ * HL_ * C_];              // P = attn @ Wp (fp32)
__device__ __nv_bfloat16 g_xb[(long)B_ * T_ * C_];      // x in bf16
__device__ __nv_bfloat16 g_WgTb[(long)HL_ * C_];        // Wg^T bf16 [N=1024,K=2048]
__device__ __nv_bfloat16 g_Gb[(long)B_ * T_ * HL_];     // softmaxed gates bf16
__device__ __nv_bfloat16 g_PTb[(long)B_ * C_ * HL_];    // P^T bf16 [b][N=2048,K=1024]

__device__ __forceinline__ uint32_t smem_u32(const void* p) {
    uint32_t a;
    asm("{ .reg .u64 t; cvta.to.shared.u64 t, %1; cvt.u32.u64 %0, t; }" : "=r"(a) : "l"(p));
    return a;
}

#define CP_ASYNC16(dst, src) \
    asm volatile("cp.async.cg.shared.global [%0], [%1], 16;" :: "r"(dst), "l"(src) : "memory")
#define CP_COMMIT() asm volatile("cp.async.commit_group;" ::: "memory")
#define CP_WAIT1()  asm volatile("cp.async.wait_group 1;" ::: "memory")

#define LDMATRIX_X4(r0, r1, r2, r3, addr) \
    asm volatile("ldmatrix.sync.aligned.m8n8.x4.shared.b16 {%0,%1,%2,%3}, [%4];" \
        : "=r"(r0), "=r"(r1), "=r"(r2), "=r"(r3) : "r"(addr))

__device__ __forceinline__ void mma_bf16(
    float& d0, float& d1, float& d2, float& d3,
    uint32_t a0, uint32_t a1, uint32_t a2, uint32_t a3,
    uint32_t b0, uint32_t b1)
{
    asm volatile(
        "mma.sync.aligned.m16n8k16.row.col.f32.bf16.bf16.f32 "
        "{%0,%1,%2,%3}, {%4,%5,%6,%7}, {%8,%9}, {%0,%1,%2,%3};"
        : "+f"(d0), "+f"(d1), "+f"(d2), "+f"(d3)
        : "r"(a0), "r"(a1), "r"(a2), "r"(a3), "r"(b0), "r"(b1));
}

// ============================================================================
// bf16 mma.sync GEMM: C[M,N] = A[M,K] @ B[N,K]^T, bf16 in, fp32 out.
// CTA 128x128, K-tile 64 (128B rows, XOR-swizzled), 3-stage cp.async pipeline.
// 8 warps (2x4), warp tile 64x32, ldmatrix fragment loads. 2 CTAs/SM.
// ============================================================================
#define STG 3
#define TILE_BYTES 16384
#define STAGE_BYTES (2 * TILE_BYTES)
#define GEMM_SMEM (STG * STAGE_BYTES)

__global__ __launch_bounds__(256, 2) void gemm_bf16(
    const __nv_bfloat16* __restrict__ A, const __nv_bfloat16* __restrict__ B,
    float* __restrict__ C,
    int K, int lda, int ldb, int ldc, long sA, long sB, long sC)
{
    extern __shared__ char sm[];
    const uint32_t sbase = smem_u32(sm);
    A += (long)blockIdx.z * sA;
    B += (long)blockIdx.z * sB;
    C += (long)blockIdx.z * sC;
    const int bm = blockIdx.y * 128;
    const int bn = blockIdx.x * 128;
    const int tid  = threadIdx.x;
    const int wid  = tid >> 5;
    const int lane = tid & 31;
    const int wm = (wid & 1) * 64;
    const int wn = (wid >> 1) * 32;

    const __nv_bfloat16* Ag = A + (long)bm * lda;
    const __nv_bfloat16* Bg = B + (long)bn * ldb;

    float acc[4][4][4];
    #pragma unroll
    for (int i = 0; i < 4; i++)
        #pragma unroll
        for (int j = 0; j < 4; j++)
            #pragma unroll
            for (int f = 0; f < 4; f++) acc[i][j][f] = 0.f;

    const int nt = K >> 6;

    auto load_stage = [&](int t) {
        const int s = t % STG;
        const uint32_t ab = sbase + s * STAGE_BYTES;
        const uint32_t bb = ab + TILE_BYTES;
        const char* as0 = (const char*)(Ag + (long)t * 64);
        const char* bs0 = (const char*)(Bg + (long)t * 64);
        #pragma unroll
        for (int q = 0; q < 4; q++) {
            int chunk = tid + q * 256;
            int row = chunk >> 3;
            int c   = chunk & 7;
            uint32_t off = row * 128 + ((c ^ (row & 7)) << 4);
            CP_ASYNC16(ab + off, as0 + (long)row * lda * 2 + c * 16);
            CP_ASYNC16(bb + off, bs0 + (long)row * ldb * 2 + c * 16);
        }
    };

    load_stage(0); CP_COMMIT();
    load_stage(1); CP_COMMIT();

    const int a_row_l  = lane & 15;
    const int a_chu_l  = lane >> 4;
    const int b_g      = lane >> 3;
    const int b_row_l  = (lane & 7) + ((b_g >> 1) << 3);
    const int b_chu_l  = b_g & 1;

    for (int t = 0; t < nt; t++) {
        CP_WAIT1();
        __syncthreads();
        if (t + 2 < nt) load_stage(t + 2);
        CP_COMMIT();

        const int s = t % STG;
        const uint32_t ab = sbase + s * STAGE_BYTES;
        const uint32_t bb = ab + TILE_BYTES;

        #pragma unroll
        for (int ks = 0; ks < 4; ks++) {
            uint32_t a[4][4], b[2][4];
            #pragma unroll
            for (int i = 0; i < 4; i++) {
                int r = wm + i * 16 + a_row_l;
                int c = ks * 2 + a_chu_l;
                uint32_t addr = ab + r * 128 + ((c ^ (r & 7)) << 4);
                LDMATRIX_X4(a[i][0], a[i][1], a[i][2], a[i][3], addr);
            }
            #pragma unroll
            for (int j2 = 0; j2 < 2; j2++) {
                int n = wn + j2 * 16 + b_row_l;
                int c = ks * 2 + b_chu_l;
                uint32_t addr = bb + n * 128 + ((c ^ (n & 7)) << 4);
                LDMATRIX_X4(b[j2][0], b[j2][1], b[j2][2], b[j2][3], addr);
            }
            #pragma unroll
            for (int i = 0; i < 4; i++)
                #pragma unroll
                for (int j = 0; j < 4; j++)
                    mma_bf16(acc[i][j][0], acc[i][j][1], acc[i][j][2], acc[i][j][3],
                             a[i][0], a[i][1], a[i][2], a[i][3],
                             b[j >> 1][(j & 1) * 2], b[j >> 1][(j & 1) * 2 + 1]);
        }
    }

    const int lr = lane >> 2;
    const int lc = lane & 3;
    #pragma unroll
    for (int i = 0; i < 4; i++) {
        int r0 = bm + wm + i * 16 + lr;
        #pragma unroll
        for (int j = 0; j < 4; j++) {
            int col = bn + wn + j * 8 + 2 * lc;
            *(float2*)(C + (long)r0 * ldc + col)       = make_float2(acc[i][j][0], acc[i][j][1]);
            *(float2*)(C + (long)(r0 + 8) * ldc + col) = make_float2(acc[i][j][2], acc[i][j][3]);
        }
    }
}

// ============================================================================
// x -> bf16 conversion (8 floats / thread, 16B stores)
// ============================================================================
__global__ void convert_x(const float* __restrict__ x)
{
    long i = (long)blockIdx.x * blockDim.x + threadIdx.x;   // over 8-float chunks
    const long n8 = (long)B_ * T_ * C_ / 8;
    if (i >= n8) return;
    float4 v0 = ((const float4*)x)[i * 2];
    float4 v1 = ((const float4*)x)[i * 2 + 1];
    __nv_bfloat162 p0 = __float22bfloat162_rn(make_float2(v0.x, v0.y));
    __nv_bfloat162 p1 = __float22bfloat162_rn(make_float2(v0.z, v0.w));
    __nv_bfloat162 p2 = __float22bfloat162_rn(make_float2(v1.x, v1.y));
    __nv_bfloat162 p3 = __float22bfloat162_rn(make_float2(v1.z, v1.w));
    uint4 o;
    o.x = *(uint32_t*)&p0; o.y = *(uint32_t*)&p1;
    o.z = *(uint32_t*)&p2; o.w = *(uint32_t*)&p3;
    ((uint4*)g_xb)[i] = o;
}

// ============================================================================
// 64x128x8 SIMT fp32 GEMM tile (small GEMMs: kv projection, P)
// ============================================================================
__device__ __forceinline__ void gemm64_body(
    const float* __restrict__ A, int lda,
    const float* __restrict__ B, int ldb,
    float* __restrict__ C, int ldc, int K, int bn)
{
    __shared__ __align__(16) float As[8][64];
    __shared__ __align__(16) float Bs[8][128];
    const int tid = threadIdx.x;
    const int arow = tid >> 2;
    const int acol = (tid & 3) * 2;
    const int brow = tid >> 5;
    const int bcol = (tid & 31) * 4;
    const int tx = (tid & 15) * 8;
    const int ty = (tid >> 4) * 4;

    float acc[4][8];
    #pragma unroll
    for (int i = 0; i < 4; i++)
        #pragma unroll
        for (int j = 0; j < 8; j++) acc[i][j] = 0.f;

    const float* Ap = A + (long)arow * lda + acol;
    const float* Bp = B + (long)brow * ldb + bn + bcol;
    for (int k0 = 0; k0 < K; k0 += 8) {
        float2 a2 = *(const float2*)Ap;
        float4 b4 = *(const float4*)Bp;
        As[acol + 0][arow] = a2.x;
        As[acol + 1][arow] = a2.y;
        *(float4*)&Bs[brow][bcol] = b4;
        __syncthreads();
        #pragma unroll
        for (int kk = 0; kk < 8; kk++) {
            float4 a0 = *(const float4*)&As[kk][ty];
            float4 b0 = *(const float4*)&Bs[kk][tx];
            float4 b1 = *(const float4*)&Bs[kk][tx + 4];
            float ar[4] = {a0.x, a0.y, a0.z, a0.w};
            float br[8] = {b0.x, b0.y, b0.z, b0.w, b1.x, b1.y, b1.z, b1.w};
            #pragma unroll
            for (int i = 0; i < 4; i++)
                #pragma unroll
                for (int j = 0; j < 8; j++)
                    acc[i][j] = fmaf(ar[i], br[j], acc[i][j]);
        }
        __syncthreads();
        Ap += 8;
        Bp += (long)8 * ldb;
    }
    #pragma unroll
    for (int i = 0; i < 4; i++) {
        float* crow = C + (long)(ty + i) * ldc + bn + tx;
        *(float4*)(crow)     = make_float4(acc[i][0], acc[i][1], acc[i][2], acc[i][3]);
        *(float4*)(crow + 4) = make_float4(acc[i][4], acc[i][5], acc[i][6], acc[i][7]);
    }
}

// kv projection, split-K x4: y = K-slice, z = b*2 + which
__global__ __launch_bounds__(256) void kv_gemm(
    const float* __restrict__ x, const float* __restrict__ Wk, const float* __restrict__ Wv)
{
    int z = blockIdx.z;
    int s = blockIdx.y;
    int b = z >> 1, which = z & 1;
    const float* A = x + (long)b * T_ * C_ + s * 512;
    const float* Bm = (which ? Wv : Wk) + (long)s * 512 * C_;
    float* Cm = (which ? g_vlin[s] : g_klin[s]) + (long)b * 64 * C_;
    gemm64_body(A, C_, Bm, C_, Cm, C_, 512, blockIdx.x * 128);
}

__global__ __launch_bounds__(256) void p_gemm(const float* __restrict__ Wp)
{
    int z = blockIdx.z;
    int b = z >> 4, h = z & 15;
    const float* A = g_attn + (long)z * L_ * D_;
    const float* Bm = Wp + (long)h * D_ * C_;
    float* Cm = g_P + (long)b * HL_ * C_ + (long)h * L_ * C_;
    gemm64_body(A, D_, Bm, C_, Cm, C_, D_, blockIdx.x * 128);
}

// ============================================================================
// transposes (-> bf16)
// ============================================================================
__global__ void transpose_wg(const float* __restrict__ Wg)
{
    __shared__ float tile[32][33];
    int k0 = blockIdx.x * 32, n0 = blockIdx.y * 32;
    int tx = threadIdx.x & 31, ty = threadIdx.x >> 5;
    #pragma unroll
    for (int i = 0; i < 32; i += 8)
        tile[ty + i][tx] = Wg[(long)(k0 + ty + i) * HL_ + n0 + tx];
    __syncthreads();
    #pragma unroll
    for (int i = 0; i < 32; i += 8)
        g_WgTb[(long)(n0 + ty + i) * C_ + k0 + tx] = __float2bfloat16(tile[tx][ty + i]);
}

__global__ void transpose_p()
{
    __shared__ float tile[32][33];
    int b = blockIdx.z;
    int hl0 = blockIdx.x * 32, c0 = blockIdx.y * 32;
    const float* P = g_P + (long)b * HL_ * C_;
    __nv_bfloat16* PT = g_PTb + (long)b * C_ * HL_;
    int tx = threadIdx.x & 31, ty = threadIdx.x >> 5;
    #pragma unroll
    for (int i = 0; i < 32; i += 8)
        tile[ty + i][tx] = P[(long)(hl0 + ty + i) * C_ + c0 + tx];
    __syncthreads();
    #pragma unroll
    for (int i = 0; i < 32; i += 8)
        PT[(long)(c0 + ty + i) * HL_ + hl0 + tx] = __float2bfloat16(tile[tx][ty + i]);
}

// ============================================================================
// rope + reduce split-K partials + transpose k,v for first 64 tokens
// ============================================================================
__global__ void rope_kernel()
{
    int idx = blockIdx.x * blockDim.x + threadIdx.x;
    if (idx >= B_ * 64 * H_ * 64) return;
    int j = idx & 63;
    int h = (idx >> 6) & 15;
    int t = (idx >> 10) & 63;
    int b = idx >> 16;
    long src = (long)(b * 64 + t) * C_ + h * D_ + 2 * j;
    float x0 = 0.f, x1 = 0.f, v0 = 0.f, v1 = 0.f;
    #pragma unroll
    for (int s = 0; s < 4; s++) {
        x0 += g_klin[s][src];
        x1 += g_klin[s][src + 1];
        v0 += g_vlin[s][src];
        v1 += g_vlin[s][src + 1];
    }
    float inv_freq = expf(-(float)j * 0.14391156831f);  // ln(10000)/64
    float ang = (float)t * inv_freq;
    float c = cosf(ang), s = sinf(ang);
    long dst = ((long)((b * H_ + h) * 64 + t)) * D_ + 2 * j;
    g_kbuf[dst] = x0 * c - x1 * s;
    g_kbuf[dst + 1] = x0 * s + x1 * c;
    g_vbuf[dst] = v0;
    g_vbuf[dst + 1] = v1;
}

// ============================================================================
// gate softmax over L=64 per (b,t,h); fp32 logits -> bf16 gates
// ============================================================================
__global__ void gate_softmax_kernel()
{
    int g = blockIdx.x * 8 + (threadIdx.x >> 5);
    if (g >= B_ * T_ * H_) return;
    int lane = threadIdx.x & 31;
    const float* ptr = g_G + (long)g * 64;
    __nv_bfloat16* po = g_Gb + (long)g * 64;
    float v0 = ptr[lane] * SCALE_;
    float v1 = ptr[lane + 32] * SCALE_;
    float m = fmaxf(v0, v1);
    #pragma unroll
    for (int o = 16; o; o >>= 1) m = fmaxf(m, __shfl_xor_sync(0xffffffffu, m, o));
    float e0 = expf(v0 - m), e1 = expf(v1 - m);
    float s = e0 + e1;
    #pragma unroll
    for (int o = 16; o; o >>= 1) s += __shfl_xor_sync(0xffffffffu, s, o);
    float inv = 1.f / s;
    po[lane]      = __float2bfloat16(e0 * inv);
    po[lane + 32] = __float2bfloat16(e1 * inv);
}

// ============================================================================
// latent attention: per (b,h) 64x64 causal softmax @ v.
// grid.x = b*H+h, grid.y = latent chunk (16 l's per block), 128 threads.
// ============================================================================
__global__ void attn_kernel(const float* __restrict__ lq)
{
    int bh = blockIdx.x;
    int b = bh >> 4, h = bh & 15;
    int l0 = blockIdx.y * 16;
    int nrows = l0 + 16;   // only rows t < l0+16 are ever needed
    __shared__ float ks[64][D_];
    __shared__ float sc[64];
    __shared__ float red[2][64];
    const float* kb = g_kbuf + (long)(bh * 64) * D_;
    const float* vb = g_vbuf + (long)(bh * 64) * D_;
    float* ao = g_attn + (long)(bh * L_) * D_;
    int tid = threadIdx.x;
    for (int i = tid; i < nrows * D_; i += 128) ks[i >> 7][i & 127] = kb[i];
    __syncthreads();

    for (int l = l0; l < l0 + 16; l++) {
        const float* q = lq + (long)(l * H_ + h) * D_;
        int t = tid & 63, part = tid >> 6;
        float dot = 0.f;
        if (t <= l) {
            int d0 = part * 64;
            #pragma unroll 8
            for (int d = d0; d < d0 + 64; d++) dot = fmaf(q[d], ks[t][d], dot);
        }
        red[part][t] = dot;
        __syncthreads();
        if (tid < 64) sc[tid] = (red[0][tid] + red[1][tid]) * SCALE_;
        __syncthreads();
        if (tid < 32) {
            float m = -1e30f;
            for (int t2 = tid; t2 <= l; t2 += 32) m = fmaxf(m, sc[t2]);
            #pragma unroll
            for (int o = 16; o; o >>= 1) m = fmaxf(m, __shfl_xor_sync(0xffffffffu, m, o));
            float s = 0.f;
            for (int t2 = tid; t2 <= l; t2 += 32) {
                float e = expf(sc[t2] - m);
                sc[t2] = e;
                s += e;
            }
            #pragma unroll
            for (int o = 16; o; o >>= 1) s += __shfl_xor_sync(0xffffffffu, s, o);
            if (tid == 0) red[0][0] = s;
        }
        __syncthreads();
        float inv = 1.f / red[0][0];
        float acc = 0.f;
        for (int t2 = 0; t2 <= l; t2++) acc = fmaf(sc[t2], vb[(long)t2 * D_ + tid], acc);
        ao[(long)l * D_ + tid] = acc * inv;
        __syncthreads();
    }
}

// ============================================================================
extern "C" void kernel_launch(void* const* d_in, const int* in_sizes, int n_in,
                              void* d_out, int out_size)
{
    const float* x  = (const float*)d_in[0];
    const float* lq = (const float*)d_in[1];
    const float* Wk = (const float*)d_in[2];
    const float* Wv = (const float*)d_in[3];
    const float* Wg = (const float*)d_in[4];
    const float* Wp = (const float*)d_in[5];
    float* out = (float*)d_out;

    float *G;
    __nv_bfloat16 *xb, *WgTb, *Gb, *PTb;
    cudaGetSymbolAddress((void**)&G, g_G);
    cudaGetSymbolAddress((void**)&xb, g_xb);
    cudaGetSymbolAddress((void**)&WgTb, g_WgTb);
    cudaGetSymbolAddress((void**)&Gb, g_Gb);
    cudaGetSymbolAddress((void**)&PTb, g_PTb);

    cudaFuncSetAttribute(gemm_bf16, cudaFuncAttributeMaxDynamicSharedMemorySize, GEMM_SMEM);

    // 1. x -> bf16
    convert_x<<<(int)(((long)B_ * T_ * C_ / 8 + 255) / 256), 256>>>(x);
    // 2. k,v for first 64 tokens per batch, split-K x4
    kv_gemm<<<dim3(16, 4, 8), 256>>>(x, Wk, Wv);
    // 3. rope + partial-sum reduce + transpose
    rope_kernel<<<(B_ * 64 * H_ * 64 + 255) / 256, 256>>>();
    // 4. WgT -> bf16
    transpose_wg<<<dim3(C_ / 32, HL_ / 32), 256>>>(Wg);
    // 5. G = x @ WgT^T (bf16 mma), [16384,1024], K=2048
    gemm_bf16<<<dim3(HL_ / 128, (B_ * T_) / 128, 1), 256, GEMM_SMEM>>>(
        xb, WgTb, G, C_, C_, C_, HL_, 0, 0, 0);
    // 6. softmax over L per (b,t,h) -> bf16 gates
    gate_softmax_kernel<<<(B_ * T_ * H_ + 7) / 8, 256>>>();
    // 7. latent attention (parallel over 4 latent chunks)
    attn_kernel<<<dim3(B_ * H_, 4), 128>>>(lq);
    // 8. P = attn @ Wp blocks (fp32)
    p_gemm<<<dim3(C_ / 128, 1, B_ * H_), 256>>>(Wp);
    // 9. PT -> bf16 per batch
    transpose_p<<<dim3(HL_ / 32, C_ / 32, B_), 256>>>();
    // 10. out = G @ PT^T per batch (bf16 mma), [4096,2048], K=1024
    gemm_bf16<<<dim3(C_ / 128, T_ / 128, B_), 256, GEMM_SMEM>>>(
        Gb, PTb, out, HL_, HL_, HL_, C_,
        (long)T_ * HL_, (long)C_ * HL_, (long)T_ * C_);
}

// round 10
// speedup vs baseline: 1.8274x; 1.0283x over previous
#include <cuda_runtime.h>
#include <cuda_bf16.h>
#include <cstdint>

// Problem constants
#define B_ 4
#define T_ 4096
#define C_ 2048
#define H_ 16
#define D_ 128
#define L_ 64
#define HL_ 1024
#define SCALE_ 0.08838834764831845f  // 1/sqrt(128)

// Scratch (device globals; no allocations allowed)
__device__ float g_klin[4][256 * C_];                   // split-K partials
__device__ float g_vlin[4][256 * C_];
__device__ float g_kbuf[B_ * H_ * 64 * D_];
__device__ float g_vbuf[B_ * H_ * 64 * D_];
__device__ float g_attn[B_ * H_ * L_ * D_];
__device__ float g_G[(long)B_ * T_ * HL_];              // gate logits (fp32)
__device__ float g_P[(long)B_ * HL_ * C_];              // P = attn @ Wp (fp32)
__device__ __nv_bfloat16 g_xb[(long)B_ * T_ * C_];      // x in bf16
__device__ __nv_bfloat16 g_WgTb[(long)HL_ * C_];        // Wg^T bf16 [N=1024,K=2048]
__device__ __nv_bfloat16 g_Gb[(long)B_ * T_ * HL_];     // softmaxed gates bf16
__device__ __nv_bfloat16 g_PTb[(long)B_ * C_ * HL_];    // P^T bf16 [b][N=2048,K=1024]

__device__ __forceinline__ uint32_t smem_u32(const void* p) {
    uint32_t a;
    asm("{ .reg .u64 t; cvta.to.shared.u64 t, %1; cvt.u32.u64 %0, t; }" : "=r"(a) : "l"(p));
    return a;
}

#define CP_ASYNC16(dst, src) \
    asm volatile("cp.async.cg.shared.global [%0], [%1], 16;" :: "r"(dst), "l"(src) : "memory")
#define CP_COMMIT() asm volatile("cp.async.commit_group;" ::: "memory")
#define CP_WAIT1()  asm volatile("cp.async.wait_group 1;" ::: "memory")

#define LDMATRIX_X4(r0, r1, r2, r3, addr) \
    asm volatile("ldmatrix.sync.aligned.m8n8.x4.shared.b16 {%0,%1,%2,%3}, [%4];" \
        : "=r"(r0), "=r"(r1), "=r"(r2), "=r"(r3) : "r"(addr))

__device__ __forceinline__ void mma_bf16(
    float& d0, float& d1, float& d2, float& d3,
    uint32_t a0, uint32_t a1, uint32_t a2, uint32_t a3,
    uint32_t b0, uint32_t b1)
{
    asm volatile(
        "mma.sync.aligned.m16n8k16.row.col.f32.bf16.bf16.f32 "
        "{%0,%1,%2,%3}, {%4,%5,%6,%7}, {%8,%9}, {%0,%1,%2,%3};"
        : "+f"(d0), "+f"(d1), "+f"(d2), "+f"(d3)
        : "r"(a0), "r"(a1), "r"(a2), "r"(a3), "r"(b0), "r"(b1));
}

// ============================================================================
// bf16 mma.sync GEMM: C[M,N] = A[M,K] @ B[N,K]^T, bf16 in, fp32 out.
// CTA 128x128, K-tile 64 (128B rows, XOR-swizzled), 3-stage cp.async pipeline.
// 8 warps (2x4), warp tile 64x32, ldmatrix fragment loads. 2 CTAs/SM.
// ============================================================================
#define STG 3
#define TILE_BYTES 16384
#define STAGE_BYTES (2 * TILE_BYTES)
#define GEMM_SMEM (STG * STAGE_BYTES)

__global__ __launch_bounds__(256, 2) void gemm_bf16(
    const __nv_bfloat16* __restrict__ A, const __nv_bfloat16* __restrict__ B,
    float* __restrict__ C,
    int K, int lda, int ldb, int ldc, long sA, long sB, long sC)
{
    extern __shared__ char sm[];
    const uint32_t sbase = smem_u32(sm);
    A += (long)blockIdx.z * sA;
    B += (long)blockIdx.z * sB;
    C += (long)blockIdx.z * sC;
    const int bm = blockIdx.y * 128;
    const int bn = blockIdx.x * 128;
    const int tid  = threadIdx.x;
    const int wid  = tid >> 5;
    const int lane = tid & 31;
    const int wm = (wid & 1) * 64;
    const int wn = (wid >> 1) * 32;

    const __nv_bfloat16* Ag = A + (long)bm * lda;
    const __nv_bfloat16* Bg = B + (long)bn * ldb;

    float acc[4][4][4];
    #pragma unroll
    for (int i = 0; i < 4; i++)
        #pragma unroll
        for (int j = 0; j < 4; j++)
            #pragma unroll
            for (int f = 0; f < 4; f++) acc[i][j][f] = 0.f;

    const int nt = K >> 6;

    auto load_stage = [&](int t) {
        const int s = t % STG;
        const uint32_t ab = sbase + s * STAGE_BYTES;
        const uint32_t bb = ab + TILE_BYTES;
        const char* as0 = (const char*)(Ag + (long)t * 64);
        const char* bs0 = (const char*)(Bg + (long)t * 64);
        #pragma unroll
        for (int q = 0; q < 4; q++) {
            int chunk = tid + q * 256;
            int row = chunk >> 3;
            int c   = chunk & 7;
            uint32_t off = row * 128 + ((c ^ (row & 7)) << 4);
            CP_ASYNC16(ab + off, as0 + (long)row * lda * 2 + c * 16);
            CP_ASYNC16(bb + off, bs0 + (long)row * ldb * 2 + c * 16);
        }
    };

    load_stage(0); CP_COMMIT();
    load_stage(1); CP_COMMIT();

    const int a_row_l  = lane & 15;
    const int a_chu_l  = lane >> 4;
    const int b_g      = lane >> 3;
    const int b_row_l  = (lane & 7) + ((b_g >> 1) << 3);
    const int b_chu_l  = b_g & 1;

    for (int t = 0; t < nt; t++) {
        CP_WAIT1();
        __syncthreads();
        if (t + 2 < nt) load_stage(t + 2);
        CP_COMMIT();

        const int s = t % STG;
        const uint32_t ab = sbase + s * STAGE_BYTES;
        const uint32_t bb = ab + TILE_BYTES;

        #pragma unroll
        for (int ks = 0; ks < 4; ks++) {
            uint32_t a[4][4], b[2][4];
            #pragma unroll
            for (int i = 0; i < 4; i++) {
                int r = wm + i * 16 + a_row_l;
                int c = ks * 2 + a_chu_l;
                uint32_t addr = ab + r * 128 + ((c ^ (r & 7)) << 4);
                LDMATRIX_X4(a[i][0], a[i][1], a[i][2], a[i][3], addr);
            }
            #pragma unroll
            for (int j2 = 0; j2 < 2; j2++) {
                int n = wn + j2 * 16 + b_row_l;
                int c = ks * 2 + b_chu_l;
                uint32_t addr = bb + n * 128 + ((c ^ (n & 7)) << 4);
                LDMATRIX_X4(b[j2][0], b[j2][1], b[j2][2], b[j2][3], addr);
            }
            #pragma unroll
            for (int i = 0; i < 4; i++)
                #pragma unroll
                for (int j = 0; j < 4; j++)
                    mma_bf16(acc[i][j][0], acc[i][j][1], acc[i][j][2], acc[i][j][3],
                             a[i][0], a[i][1], a[i][2], a[i][3],
                             b[j >> 1][(j & 1) * 2], b[j >> 1][(j & 1) * 2 + 1]);
        }
    }

    const int lr = lane >> 2;
    const int lc = lane & 3;
    #pragma unroll
    for (int i = 0; i < 4; i++) {
        int r0 = bm + wm + i * 16 + lr;
        #pragma unroll
        for (int j = 0; j < 4; j++) {
            int col = bn + wn + j * 8 + 2 * lc;
            *(float2*)(C + (long)r0 * ldc + col)       = make_float2(acc[i][j][0], acc[i][j][1]);
            *(float2*)(C + (long)(r0 + 8) * ldc + col) = make_float2(acc[i][j][2], acc[i][j][3]);
        }
    }
}

// ============================================================================
// x -> bf16 conversion (8 floats / thread, 16B stores)
// ============================================================================
__global__ void convert_x(const float* __restrict__ x)
{
    long i = (long)blockIdx.x * blockDim.x + threadIdx.x;   // over 8-float chunks
    const long n8 = (long)B_ * T_ * C_ / 8;
    if (i >= n8) return;
    float4 v0 = ((const float4*)x)[i * 2];
    float4 v1 = ((const float4*)x)[i * 2 + 1];
    __nv_bfloat162 p0 = __float22bfloat162_rn(make_float2(v0.x, v0.y));
    __nv_bfloat162 p1 = __float22bfloat162_rn(make_float2(v0.z, v0.w));
    __nv_bfloat162 p2 = __float22bfloat162_rn(make_float2(v1.x, v1.y));
    __nv_bfloat162 p3 = __float22bfloat162_rn(make_float2(v1.z, v1.w));
    uint4 o;
    o.x = *(uint32_t*)&p0; o.y = *(uint32_t*)&p1;
    o.z = *(uint32_t*)&p2; o.w = *(uint32_t*)&p3;
    ((uint4*)g_xb)[i] = o;
}

// ============================================================================
// 64x128x8 SIMT fp32 GEMM tile (small GEMMs: kv projection, P)
// ============================================================================
__device__ __forceinline__ void gemm64_body(
    const float* __restrict__ A, int lda,
    const float* __restrict__ B, int ldb,
    float* __restrict__ C, int ldc, int K, int bn)
{
    __shared__ __align__(16) float As[8][64];
    __shared__ __align__(16) float Bs[8][128];
    const int tid = threadIdx.x;
    const int arow = tid >> 2;
    const int acol = (tid & 3) * 2;
    const int brow = tid >> 5;
    const int bcol = (tid & 31) * 4;
    const int tx = (tid & 15) * 8;
    const int ty = (tid >> 4) * 4;

    float acc[4][8];
    #pragma unroll
    for (int i = 0; i < 4; i++)
        #pragma unroll
        for (int j = 0; j < 8; j++) acc[i][j] = 0.f;

    const float* Ap = A + (long)arow * lda + acol;
    const float* Bp = B + (long)brow * ldb + bn + bcol;
    for (int k0 = 0; k0 < K; k0 += 8) {
        float2 a2 = *(const float2*)Ap;
        float4 b4 = *(const float4*)Bp;
        As[acol + 0][arow] = a2.x;
        As[acol + 1][arow] = a2.y;
        *(float4*)&Bs[brow][bcol] = b4;
        __syncthreads();
        #pragma unroll
        for (int kk = 0; kk < 8; kk++) {
            float4 a0 = *(const float4*)&As[kk][ty];
            float4 b0 = *(const float4*)&Bs[kk][tx];
            float4 b1 = *(const float4*)&Bs[kk][tx + 4];
            float ar[4] = {a0.x, a0.y, a0.z, a0.w};
            float br[8] = {b0.x, b0.y, b0.z, b0.w, b1.x, b1.y, b1.z, b1.w};
            #pragma unroll
            for (int i = 0; i < 4; i++)
                #pragma unroll
                for (int j = 0; j < 8; j++)
                    acc[i][j] = fmaf(ar[i], br[j], acc[i][j]);
        }
        __syncthreads();
        Ap += 8;
        Bp += (long)8 * ldb;
    }
    #pragma unroll
    for (int i = 0; i < 4; i++) {
        float* crow = C + (long)(ty + i) * ldc + bn + tx;
        *(float4*)(crow)     = make_float4(acc[i][0], acc[i][1], acc[i][2], acc[i][3]);
        *(float4*)(crow + 4) = make_float4(acc[i][4], acc[i][5], acc[i][6], acc[i][7]);
    }
}

// kv projection, split-K x4: y = K-slice, z = b*2 + which
__global__ __launch_bounds__(256) void kv_gemm(
    const float* __restrict__ x, const float* __restrict__ Wk, const float* __restrict__ Wv)
{
    int z = blockIdx.z;
    int s = blockIdx.y;
    int b = z >> 1, which = z & 1;
    const float* A = x + (long)b * T_ * C_ + s * 512;
    const float* Bm = (which ? Wv : Wk) + (long)s * 512 * C_;
    float* Cm = (which ? g_vlin[s] : g_klin[s]) + (long)b * 64 * C_;
    gemm64_body(A, C_, Bm, C_, Cm, C_, 512, blockIdx.x * 128);
}

__global__ __launch_bounds__(256) void p_gemm(const float* __restrict__ Wp)
{
    int z = blockIdx.z;
    int b = z >> 4, h = z & 15;
    const float* A = g_attn + (long)z * L_ * D_;
    const float* Bm = Wp + (long)h * D_ * C_;
    float* Cm = g_P + (long)b * HL_ * C_ + (long)h * L_ * C_;
    gemm64_body(A, D_, Bm, C_, Cm, C_, D_, blockIdx.x * 128);
}

// ============================================================================
// transposes (-> bf16)
// ============================================================================
__global__ void transpose_wg(const float* __restrict__ Wg)
{
    __shared__ float tile[32][33];
    int k0 = blockIdx.x * 32, n0 = blockIdx.y * 32;
    int tx = threadIdx.x & 31, ty = threadIdx.x >> 5;
    #pragma unroll
    for (int i = 0; i < 32; i += 8)
        tile[ty + i][tx] = Wg[(long)(k0 + ty + i) * HL_ + n0 + tx];
    __syncthreads();
    #pragma unroll
    for (int i = 0; i < 32; i += 8)
        g_WgTb[(long)(n0 + ty + i) * C_ + k0 + tx] = __float2bfloat16(tile[tx][ty + i]);
}

__global__ void transpose_p()
{
    __shared__ float tile[32][33];
    int b = blockIdx.z;
    int hl0 = blockIdx.x * 32, c0 = blockIdx.y * 32;
    const float* P = g_P + (long)b * HL_ * C_;
    __nv_bfloat16* PT = g_PTb + (long)b * C_ * HL_;
    int tx = threadIdx.x & 31, ty = threadIdx.x >> 5;
    #pragma unroll
    for (int i = 0; i < 32; i += 8)
        tile[ty + i][tx] = P[(long)(hl0 + ty + i) * C_ + c0 + tx];
    __syncthreads();
    #pragma unroll
    for (int i = 0; i < 32; i += 8)
        PT[(long)(c0 + ty + i) * HL_ + hl0 + tx] = __float2bfloat16(tile[tx][ty + i]);
}

// ============================================================================
// rope + reduce split-K partials + transpose k,v for first 64 tokens
// ============================================================================
__global__ void rope_kernel()
{
    int idx = blockIdx.x * blockDim.x + threadIdx.x;
    if (idx >= B_ * 64 * H_ * 64) return;
    int j = idx & 63;
    int h = (idx >> 6) & 15;
    int t = (idx >> 10) & 63;
    int b = idx >> 16;
    long src = (long)(b * 64 + t) * C_ + h * D_ + 2 * j;
    float x0 = 0.f, x1 = 0.f, v0 = 0.f, v1 = 0.f;
    #pragma unroll
    for (int s = 0; s < 4; s++) {
        x0 += g_klin[s][src];
        x1 += g_klin[s][src + 1];
        v0 += g_vlin[s][src];
        v1 += g_vlin[s][src + 1];
    }
    float inv_freq = expf(-(float)j * 0.14391156831f);  // ln(10000)/64
    float ang = (float)t * inv_freq;
    float c = cosf(ang), s = sinf(ang);
    long dst = ((long)((b * H_ + h) * 64 + t)) * D_ + 2 * j;
    g_kbuf[dst] = x0 * c - x1 * s;
    g_kbuf[dst + 1] = x0 * s + x1 * c;
    g_vbuf[dst] = v0;
    g_vbuf[dst + 1] = v1;
}

// ============================================================================
// gate softmax over L=64 per (b,t,h); fp32 logits -> bf16 gates
// ============================================================================
__global__ void gate_softmax_kernel()
{
    int g = blockIdx.x * 8 + (threadIdx.x >> 5);
    if (g >= B_ * T_ * H_) return;
    int lane = threadIdx.x & 31;
    const float* ptr = g_G + (long)g * 64;
    __nv_bfloat16* po = g_Gb + (long)g * 64;
    float v0 = ptr[lane] * SCALE_;
    float v1 = ptr[lane + 32] * SCALE_;
    float m = fmaxf(v0, v1);
    #pragma unroll
    for (int o = 16; o; o >>= 1) m = fmaxf(m, __shfl_xor_sync(0xffffffffu, m, o));
    float e0 = expf(v0 - m), e1 = expf(v1 - m);
    float s = e0 + e1;
    #pragma unroll
    for (int o = 16; o; o >>= 1) s += __shfl_xor_sync(0xffffffffu, s, o);
    float inv = 1.f / s;
    po[lane]      = __float2bfloat16(e0 * inv);
    po[lane + 32] = __float2bfloat16(e1 * inv);
}

// ============================================================================
// latent attention: per (b,h) 64x64 causal softmax @ v.
// grid.x = b*H+h, grid.y = latent chunk (16 l's per block), 128 threads.
// ============================================================================
__global__ void attn_kernel(const float* __restrict__ lq)
{
    int bh = blockIdx.x;
    int b = bh >> 4, h = bh & 15;
    int l0 = blockIdx.y * 16;
    int nrows = l0 + 16;   // only rows t < l0+16 are ever needed
    __shared__ float ks[64][D_];
    __shared__ float sc[64];
    __shared__ float red[2][64];
    const float* kb = g_kbuf + (long)(bh * 64) * D_;
    const float* vb = g_vbuf + (long)(bh * 64) * D_;
    float* ao = g_attn + (long)(bh * L_) * D_;
    int tid = threadIdx.x;
    for (int i = tid; i < nrows * D_; i += 128) ks[i >> 7][i & 127] = kb[i];
    __syncthreads();

    for (int l = l0; l < l0 + 16; l++) {
        const float* q = lq + (long)(l * H_ + h) * D_;
        int t = tid & 63, part = tid >> 6;
        float dot = 0.f;
        if (t <= l) {
            int d0 = part * 64;
            #pragma unroll 8
            for (int d = d0; d < d0 + 64; d++) dot = fmaf(q[d], ks[t][d], dot);
        }
        red[part][t] = dot;
        __syncthreads();
        if (tid < 64) sc[tid] = (red[0][tid] + red[1][tid]) * SCALE_;
        __syncthreads();
        if (tid < 32) {
            float m = -1e30f;
            for (int t2 = tid; t2 <= l; t2 += 32) m = fmaxf(m, sc[t2]);
            #pragma unroll
            for (int o = 16; o; o >>= 1) m = fmaxf(m, __shfl_xor_sync(0xffffffffu, m, o));
            float s = 0.f;
            for (int t2 = tid; t2 <= l; t2 += 32) {
                float e = expf(sc[t2] - m);
                sc[t2] = e;
                s += e;
            }
            #pragma unroll
            for (int o = 16; o; o >>= 1) s += __shfl_xor_sync(0xffffffffu, s, o);
            if (tid == 0) red[0][0] = s;
        }
        __syncthreads();
        float inv = 1.f / red[0][0];
        float acc = 0.f;
        for (int t2 = 0; t2 <= l; t2++) acc = fmaf(sc[t2], vb[(long)t2 * D_ + tid], acc);
        ao[(long)l * D_ + tid] = acc * inv;
        __syncthreads();
    }
}

// ============================================================================
extern "C" void kernel_launch(void* const* d_in, const int* in_sizes, int n_in,
                              void* d_out, int out_size)
{
    const float* x  = (const float*)d_in[0];
    const float* lq = (const float*)d_in[1];
    const float* Wk = (const float*)d_in[2];
    const float* Wv = (const float*)d_in[3];
    const float* Wg = (const float*)d_in[4];
    const float* Wp = (const float*)d_in[5];
    float* out = (float*)d_out;

    float *G;
    __nv_bfloat16 *xb, *WgTb, *Gb, *PTb;
    cudaGetSymbolAddress((void**)&G, g_G);
    cudaGetSymbolAddress((void**)&xb, g_xb);
    cudaGetSymbolAddress((void**)&WgTb, g_WgTb);
    cudaGetSymbolAddress((void**)&Gb, g_Gb);
    cudaGetSymbolAddress((void**)&PTb, g_PTb);

    cudaFuncSetAttribute(gemm_bf16, cudaFuncAttributeMaxDynamicSharedMemorySize, GEMM_SMEM);

    // Fork a side stream for the attention chain (independent of GEMM1 path).
    // kernel_launch only runs for correctness + capture, so per-call creation
    // of a stream/events is cheap and keeps the function stateless.
    cudaStream_t s2;
    cudaStreamCreateWithFlags(&s2, cudaStreamNonBlocking);
    cudaEvent_t evFork, evJoin;
    cudaEventCreateWithFlags(&evFork, cudaEventDisableTiming);
    cudaEventCreateWithFlags(&evJoin, cudaEventDisableTiming);

    cudaEventRecord(evFork, 0);
    cudaStreamWaitEvent(s2, evFork, 0);

    // --- side stream: kv projection -> rope -> attention -> P -> P^T ---
    kv_gemm<<<dim3(16, 4, 8), 256, 0, s2>>>(x, Wk, Wv);
    rope_kernel<<<(B_ * 64 * H_ * 64 + 255) / 256, 256, 0, s2>>>();
    attn_kernel<<<dim3(B_ * H_, 4), 128, 0, s2>>>(lq);
    p_gemm<<<dim3(C_ / 128, 1, B_ * H_), 256, 0, s2>>>(Wp);
    transpose_p<<<dim3(HL_ / 32, C_ / 32, B_), 256, 0, s2>>>();
    cudaEventRecord(evJoin, s2);

    // --- main stream: x->bf16, Wg^T, GEMM1, gate softmax ---
    convert_x<<<(int)(((long)B_ * T_ * C_ / 8 + 255) / 256), 256>>>(x);
    transpose_wg<<<dim3(C_ / 32, HL_ / 32), 256>>>(Wg);
    gemm_bf16<<<dim3(HL_ / 128, (B_ * T_) / 128, 1), 256, GEMM_SMEM>>>(
        xb, WgTb, G, C_, C_, C_, HL_, 0, 0, 0);
    gate_softmax_kernel<<<(B_ * T_ * H_ + 7) / 8, 256>>>();

    // join: GEMM2 needs both Gb (main) and PTb (side)
    cudaStreamWaitEvent(0, evJoin, 0);
    gemm_bf16<<<dim3(C_ / 128, T_ / 128, B_), 256, GEMM_SMEM>>>(
        Gb, PTb, out, HL_, HL_, HL_, C_,
        (long)T_ * HL_, (long)C_ * HL_, (long)T_ * C_);
}